// round 2
// baseline (speedup 1.0000x reference)
#include <cuda_runtime.h>

#define BB 2
#define FF 48
#define CC 96
#define HH 320
#define WW 320
#define HWW (HH*WW)

// Scratch activations (pre-activation conv outputs, 96-channel real form)
__device__ float g_act0[BB*CC*HWW];
__device__ float g_act1[BB*CC*HWW];
// Repacked combined weights: layout [cin][tap][cout]
__device__ float g_w0[2*9*CC];
__device__ float g_w1[CC*9*CC];
__device__ float g_w2[CC*9*CC];
__device__ float g_b0[CC];
__device__ float g_b1[CC];
__device__ float g_b2[CC];

__device__ __forceinline__ float sigma_f(float u) {
    // smooth ReLU: relu outside |u|<=1e-3, 250*u^2 + 0.5*u + 0.25e-3 inside
    float quad = fmaf(u, fmaf(u, 250.0f, 0.5f), 0.00025f);
    return (fabsf(u) > 0.001f) ? fmaxf(u, 0.0f) : quad;
}

// ---------------------------------------------------------------------------
// Weight repack: complex (wr, wi) [F,Fin,3,3] -> real block [cin][tap][cout]
//   cout<48 & cin<48  :  wr      |  cout<48 & cin>=48 : -wi
//   cout>=48 & cin<48 :  wi      |  cout>=48 & cin>=48:  wr
// ---------------------------------------------------------------------------
__global__ void repack_big(const float* __restrict__ wr, const float* __restrict__ wi,
                           const float* __restrict__ br, const float* __restrict__ bi,
                           int which) {
    float* dw = (which == 1) ? g_w1 : g_w2;
    float* db = (which == 1) ? g_b1 : g_b2;
    int idx = blockIdx.x * blockDim.x + threadIdx.x;
    if (idx < CC) db[idx] = (idx < FF) ? br[idx] : bi[idx - FF];
    if (idx >= CC*9*CC) return;
    int cout = idx % CC;
    int t    = (idx / CC) % 9;
    int cin  = idx / (9*CC);
    int fo = cout % FF, fi = cin % FF;
    const float* src = ((cout < FF) == (cin < FF)) ? wr : wi;
    float v = src[(fo*FF + fi)*9 + t];
    if (cout < FF && cin >= FF) v = -v;
    dw[idx] = v;
}

__global__ void repack_small(const float* __restrict__ wr, const float* __restrict__ wi,
                             const float* __restrict__ br, const float* __restrict__ bi) {
    int idx = blockIdx.x * blockDim.x + threadIdx.x;
    if (idx < CC) g_b0[idx] = (idx < FF) ? br[idx] : bi[idx - FF];
    if (idx >= 2*9*CC) return;
    int cout = idx % CC;
    int t    = (idx / CC) % 9;
    int cin  = idx / (9*CC);   // 0 = real plane, 1 = imag plane
    int fo = cout % FF;
    const float* src = ((cout < FF) == (cin == 0)) ? wr : wi;
    float v = src[fo*9 + t];
    if (cout < FF && cin == 1) v = -v;
    g_w0[idx] = v;
}

// ---------------------------------------------------------------------------
// Layer 0: conv 2 -> 96 (tiny: 0.7 GF). One thread = one pixel, all 96 couts.
// Writes g_act0 and the l=0 slice of out.
// ---------------------------------------------------------------------------
__global__ __launch_bounds__(256)
void conv0_kernel(const float* __restrict__ xr, const float* __restrict__ xi,
                  float* __restrict__ out) {
    __shared__ float sw[2*9*CC];
    __shared__ float sb[CC];
    for (int i = threadIdx.x; i < 2*9*CC; i += 256) sw[i] = g_w0[i];
    if (threadIdx.x < CC) sb[threadIdx.x] = g_b0[threadIdx.x];
    __syncthreads();

    int pix = blockIdx.x * 256 + threadIdx.x;
    if (pix >= BB*HWW) return;
    int b = pix / HWW;
    int p = pix - b*HWW;
    int y = p / WW, x = p - y*WW;

    const float* x0 = xr + b*HWW;
    const float* x1 = xi + b*HWW;
    float in[18];
    #pragma unroll
    for (int dy = 0; dy < 3; dy++) {
        #pragma unroll
        for (int dx = 0; dx < 3; dx++) {
            int yy = y + dy - 1, xx = x + dx - 1;
            bool ok = (yy >= 0) && (yy < HH) && (xx >= 0) && (xx < WW);
            in[dy*3 + dx]     = ok ? x0[yy*WW + xx] : 0.0f;
            in[9 + dy*3 + dx] = ok ? x1[yy*WW + xx] : 0.0f;
        }
    }

    #pragma unroll 4
    for (int cout = 0; cout < CC; cout++) {
        float acc = sb[cout];
        #pragma unroll
        for (int t = 0; t < 18; t++)
            acc = fmaf(in[t], sw[t*CC + cout], acc);
        g_act0[(b*CC + cout)*HWW + p] = acc;
        int f = cout % FF, c2 = cout / FF;
        out[((b*FF + f)*HWW + p)*2 + c2] = acc;
    }
}

// ---------------------------------------------------------------------------
// Layers 1,2: conv 96 -> 96 (the hot kernel, ~34 GF each).
// Block = 192 threads (6 warps). Warp w owns couts [16w, 16w+16).
// Lane: prow = lane>>2 (8 rows), pcol = (lane&3)*4 (4 px strip).
// Tile = 16(W) x 8(H) pixels, all 96 couts. cin chunked by 8 through smem.
// sigma fused into the smem input load; bias + output-layout fused epilogue.
// ---------------------------------------------------------------------------
#define TW 16
#define TH 8
#define KC 8
#define SPITCH 20

template<int LAYER>
__global__ __launch_bounds__(192, 2)
void convL_kernel(float* __restrict__ out) {
    const float* __restrict__ act_in = (LAYER == 1) ? g_act0 : g_act1;
    const float* __restrict__ wg     = (LAYER == 1) ? g_w1 : g_w2;
    const float* __restrict__ bg     = (LAYER == 1) ? g_b1 : g_b2;

    __shared__ float s_in[KC*10*SPITCH];   // 8 cin x (8+2) rows x (16+2 used)
    __shared__ float s_w[KC*9*CC];         // 8 cin x 9 taps x 96 couts

    int tx0 = blockIdx.x * TW;
    int ty0 = blockIdx.y * TH;
    int b   = blockIdx.z;
    int tid = threadIdx.x;
    int warp = tid >> 5, lane = tid & 31;
    int prow = lane >> 2;
    int pcol = (lane & 3) << 2;
    int cout0 = warp * 16;

    float acc[16][4];
    #pragma unroll
    for (int j = 0; j < 16; j++) {
        acc[j][0] = 0.f; acc[j][1] = 0.f; acc[j][2] = 0.f; acc[j][3] = 0.f;
    }

    for (int c0 = 0; c0 < CC; c0 += KC) {
        // weights: contiguous, coalesced (hits L2 after first wave)
        const float* wsrc = wg + c0*9*CC;
        #pragma unroll
        for (int i = tid; i < KC*9*CC; i += 192) s_w[i] = wsrc[i];
        // inputs with halo + fused sigma
        #pragma unroll
        for (int i = tid; i < KC*10*18; i += 192) {
            int col = i % 18;
            int rem = i / 18;
            int row = rem % 10;
            int kc  = rem / 10;
            int gy = ty0 + row - 1;
            int gx = tx0 + col - 1;
            float v = 0.0f;
            if (gy >= 0 && gy < HH && gx >= 0 && gx < WW) {
                float u = act_in[((b*CC + c0 + kc)*HH + gy)*WW + gx];
                v = sigma_f(u);
            }
            s_in[(kc*10 + row)*SPITCH + col] = v;
        }
        __syncthreads();

        #pragma unroll
        for (int kc = 0; kc < KC; kc++) {
            float inr[3][6];
            #pragma unroll
            for (int r = 0; r < 3; r++)
                #pragma unroll
                for (int cc6 = 0; cc6 < 6; cc6++)
                    inr[r][cc6] = s_in[(kc*10 + prow + r)*SPITCH + pcol + cc6];

            #pragma unroll
            for (int dy = 0; dy < 3; dy++) {
                #pragma unroll
                for (int dx = 0; dx < 3; dx++) {
                    float w[16];
                    #pragma unroll
                    for (int j = 0; j < 16; j++)
                        w[j] = s_w[(kc*9 + dy*3 + dx)*CC + cout0 + j];  // warp-uniform -> broadcast
                    #pragma unroll
                    for (int j = 0; j < 16; j++)
                        #pragma unroll
                        for (int p = 0; p < 4; p++)
                            acc[j][p] = fmaf(w[j], inr[dy][dx + p], acc[j][p]);
                }
            }
        }
        __syncthreads();
    }

    // epilogue: bias, scratch store (layer 1 only), output-layout store
    int px = tx0 + pcol;
    int py = ty0 + prow;
    int p  = py*WW + px;
    #pragma unroll
    for (int j = 0; j < 16; j++) {
        int cout = cout0 + j;
        float bias = __ldg(&bg[cout]);
        float v0 = acc[j][0] + bias, v1 = acc[j][1] + bias;
        float v2 = acc[j][2] + bias, v3 = acc[j][3] + bias;
        if (LAYER == 1) {
            float4* dst = reinterpret_cast<float4*>(&g_act1[(b*CC + cout)*HWW + p]);
            *dst = make_float4(v0, v1, v2, v3);
        }
        int f = cout % FF, c2 = cout / FF;
        int obase = (((LAYER*BB + b)*FF + f)*HWW + p)*2 + c2;
        out[obase]     = v0;
        out[obase + 2] = v1;
        out[obase + 4] = v2;
        out[obase + 6] = v3;
    }
}

extern "C" void kernel_launch(void* const* d_in, const int* in_sizes, int n_in,
                              void* d_out, int out_size) {
    const float* x_real = (const float*)d_in[0];
    const float* x_imag = (const float*)d_in[1];
    const float* w0r = (const float*)d_in[2];
    const float* w0i = (const float*)d_in[3];
    const float* b0r = (const float*)d_in[4];
    const float* b0i = (const float*)d_in[5];
    const float* w1r = (const float*)d_in[6];
    const float* w1i = (const float*)d_in[7];
    const float* b1r = (const float*)d_in[8];
    const float* b1i = (const float*)d_in[9];
    const float* w2r = (const float*)d_in[10];
    const float* w2i = (const float*)d_in[11];
    const float* b2r = (const float*)d_in[12];
    const float* b2i = (const float*)d_in[13];
    float* out = (float*)d_out;

    repack_small<<<(2*9*CC + 255)/256, 256>>>(w0r, w0i, b0r, b0i);
    repack_big<<<(CC*9*CC + 255)/256, 256>>>(w1r, w1i, b1r, b1i, 1);
    repack_big<<<(CC*9*CC + 255)/256, 256>>>(w2r, w2i, b2r, b2i, 2);

    conv0_kernel<<<(BB*HWW + 255)/256, 256>>>(x_real, x_imag, out);

    dim3 grid(WW/TW, HH/TH, BB);
    convL_kernel<1><<<grid, 192>>>(out);
    convL_kernel<2><<<grid, 192>>>(out);
}

// round 4
// speedup vs baseline: 1.0665x; 1.0665x over previous
#include <cuda_runtime.h>

#define BB 2
#define FF 48
#define CC 96
#define HH 320
#define WW 320
#define HWW (HH*WW)

typedef unsigned long long u64;

// Scratch activations (pre-activation conv outputs, 96-channel real form)
__device__ float g_act0[BB*CC*HWW];
__device__ float g_act1[BB*CC*HWW];
// Repacked combined weights: layout [cin][tap][cout]
__device__ float g_w0[2*9*CC];
__device__ float g_w1[CC*9*CC];
__device__ float g_w2[CC*9*CC];
__device__ float g_b0[CC];
__device__ float g_b1[CC];
__device__ float g_b2[CC];

__device__ __forceinline__ float sigma_f(float u) {
    float quad = fmaf(u, fmaf(u, 250.0f, 0.5f), 0.00025f);
    return (fabsf(u) > 0.001f) ? fmaxf(u, 0.0f) : quad;
}

__device__ __forceinline__ u64 ffma2(u64 a, u64 b, u64 c) {
    u64 d;
    asm("fma.rn.f32x2 %0, %1, %2, %3;" : "=l"(d) : "l"(a), "l"(b), "l"(c));
    return d;
}
__device__ __forceinline__ u64 packf2(float lo, float hi) {
    u64 d;
    asm("mov.b64 %0, {%1, %2};" : "=l"(d) : "f"(lo), "f"(hi));
    return d;
}
__device__ __forceinline__ void unpackf2(u64 v, float& lo, float& hi) {
    asm("mov.b64 {%0, %1}, %2;" : "=f"(lo), "=f"(hi) : "l"(v));
}

// ---------------------------------------------------------------------------
// Weight repack: complex (wr, wi) -> real block [cin][tap][cout]
// ---------------------------------------------------------------------------
__global__ void repack_big(const float* __restrict__ wr, const float* __restrict__ wi,
                           const float* __restrict__ br, const float* __restrict__ bi,
                           int which) {
    float* dw = (which == 1) ? g_w1 : g_w2;
    float* db = (which == 1) ? g_b1 : g_b2;
    int idx = blockIdx.x * blockDim.x + threadIdx.x;
    if (idx < CC) db[idx] = (idx < FF) ? br[idx] : bi[idx - FF];
    if (idx >= CC*9*CC) return;
    int cout = idx % CC;
    int t    = (idx / CC) % 9;
    int cin  = idx / (9*CC);
    int fo = cout % FF, fi = cin % FF;
    const float* src = ((cout < FF) == (cin < FF)) ? wr : wi;
    float v = src[(fo*FF + fi)*9 + t];
    if (cout < FF && cin >= FF) v = -v;
    dw[idx] = v;
}

__global__ void repack_small(const float* __restrict__ wr, const float* __restrict__ wi,
                             const float* __restrict__ br, const float* __restrict__ bi) {
    int idx = blockIdx.x * blockDim.x + threadIdx.x;
    if (idx < CC) g_b0[idx] = (idx < FF) ? br[idx] : bi[idx - FF];
    if (idx >= 2*9*CC) return;
    int cout = idx % CC;
    int t    = (idx / CC) % 9;
    int cin  = idx / (9*CC);
    int fo = cout % FF;
    const float* src = ((cout < FF) == (cin == 0)) ? wr : wi;
    float v = src[fo*9 + t];
    if (cout < FF && cin == 1) v = -v;
    g_w0[idx] = v;
}

// ---------------------------------------------------------------------------
// Layer 0: conv 2 -> 96 (52us, 2% of total)
// ---------------------------------------------------------------------------
__global__ __launch_bounds__(256)
void conv0_kernel(const float* __restrict__ xr, const float* __restrict__ xi,
                  float* __restrict__ out) {
    __shared__ float sw[2*9*CC];
    __shared__ float sb[CC];
    for (int i = threadIdx.x; i < 2*9*CC; i += 256) sw[i] = g_w0[i];
    if (threadIdx.x < CC) sb[threadIdx.x] = g_b0[threadIdx.x];
    __syncthreads();

    int pix = blockIdx.x * 256 + threadIdx.x;
    if (pix >= BB*HWW) return;
    int b = pix / HWW;
    int p = pix - b*HWW;
    int y = p / WW, x = p - y*WW;

    const float* x0 = xr + b*HWW;
    const float* x1 = xi + b*HWW;
    float in[18];
    #pragma unroll
    for (int dy = 0; dy < 3; dy++) {
        #pragma unroll
        for (int dx = 0; dx < 3; dx++) {
            int yy = y + dy - 1, xx = x + dx - 1;
            bool ok = (yy >= 0) && (yy < HH) && (xx >= 0) && (xx < WW);
            in[dy*3 + dx]     = ok ? x0[yy*WW + xx] : 0.0f;
            in[9 + dy*3 + dx] = ok ? x1[yy*WW + xx] : 0.0f;
        }
    }

    #pragma unroll 4
    for (int cout = 0; cout < CC; cout++) {
        float acc = sb[cout];
        #pragma unroll
        for (int t = 0; t < 18; t++)
            acc = fmaf(in[t], sw[t*CC + cout], acc);
        g_act0[(b*CC + cout)*HWW + p] = acc;
        int f = cout % FF, c2 = cout / FF;
        out[((b*FF + f)*HWW + p)*2 + c2] = acc;
    }
}

// ---------------------------------------------------------------------------
// Layers 1,2: conv 96 -> 96, packed f32x2 (FFMA2) mainloop.
// Block = 192 threads (6 warps). Warp w owns couts [16w, 16w+16).
// Lane: prow = lane>>2 (8 rows), pcol = (lane&3)*4 (4-px strip = 2 f32x2 accs).
// Weights staged in smem PRE-DUPLICATED as float2(w,w) -> LDS.128 gives two
// ready FFMA2 operands. cin chunked by 4 (static smem 48KB limit).
// ---------------------------------------------------------------------------
#define TW 16
#define TH 8
#define KC 4
#define SPITCH 20

template<int LAYER>
__global__ __launch_bounds__(192, 2)
void convL_kernel(float* __restrict__ out) {
    const float* __restrict__ act_in = (LAYER == 1) ? g_act0 : g_act1;
    const float* __restrict__ wg     = (LAYER == 1) ? g_w1 : g_w2;
    const float* __restrict__ bg     = (LAYER == 1) ? g_b1 : g_b2;

    __shared__ float  s_in[KC*10*SPITCH];       // 3.2 KB
    __shared__ float2 s_w[KC*9*CC];             // 27.6 KB, each entry (w,w)

    int tx0 = blockIdx.x * TW;
    int ty0 = blockIdx.y * TH;
    int b   = blockIdx.z;
    int tid = threadIdx.x;
    int warp = tid >> 5, lane = tid & 31;
    int prow = lane >> 2;
    int pcol = (lane & 3) << 2;
    int cout0 = warp * 16;

    u64 acc[16][2];
    #pragma unroll
    for (int j = 0; j < 16; j++) { acc[j][0] = 0ull; acc[j][1] = 0ull; }

    for (int c0 = 0; c0 < CC; c0 += KC) {
        // weights: read contiguous scalar, write duplicated float2
        const float* wsrc = wg + c0*9*CC;
        #pragma unroll
        for (int i = tid; i < KC*9*CC; i += 192) {
            float w = wsrc[i];
            s_w[i] = make_float2(w, w);
        }
        // inputs with halo + fused sigma
        #pragma unroll
        for (int i = tid; i < KC*10*18; i += 192) {
            int col = i % 18;
            int rem = i / 18;
            int row = rem % 10;
            int kc  = rem / 10;
            int gy = ty0 + row - 1;
            int gx = tx0 + col - 1;
            float v = 0.0f;
            if (gy >= 0 && gy < HH && gx >= 0 && gx < WW) {
                float u = act_in[((b*CC + c0 + kc)*HH + gy)*WW + gx];
                v = sigma_f(u);
            }
            s_in[(kc*10 + row)*SPITCH + col] = v;
        }
        __syncthreads();

        #pragma unroll
        for (int kc = 0; kc < KC; kc++) {
            #pragma unroll
            for (int dy = 0; dy < 3; dy++) {
                // load this input row (6 values), build 5 sliding pairs
                float inr[6];
                #pragma unroll
                for (int c = 0; c < 6; c++)
                    inr[c] = s_in[(kc*10 + prow + dy)*SPITCH + pcol + c];
                u64 pr[5];
                #pragma unroll
                for (int c = 0; c < 5; c++) pr[c] = packf2(inr[c], inr[c+1]);

                #pragma unroll
                for (int dx = 0; dx < 3; dx++) {
                    const ulonglong2* wp = reinterpret_cast<const ulonglong2*>(
                        &s_w[(kc*9 + dy*3 + dx)*CC + cout0]);   // warp-uniform, 16B aligned
                    u64 a0 = pr[dx], a1 = pr[dx + 2];
                    #pragma unroll
                    for (int j2 = 0; j2 < 8; j2++) {
                        ulonglong2 w2 = wp[j2];                 // (w_{2j2} dup, w_{2j2+1} dup)
                        acc[2*j2  ][0] = ffma2(w2.x, a0, acc[2*j2  ][0]);
                        acc[2*j2  ][1] = ffma2(w2.x, a1, acc[2*j2  ][1]);
                        acc[2*j2+1][0] = ffma2(w2.y, a0, acc[2*j2+1][0]);
                        acc[2*j2+1][1] = ffma2(w2.y, a1, acc[2*j2+1][1]);
                    }
                }
            }
        }
        __syncthreads();
    }

    // epilogue: unpack, bias, scratch store (layer 1), output-layout store
    int px = tx0 + pcol;
    int py = ty0 + prow;
    int p  = py*WW + px;
    #pragma unroll
    for (int j = 0; j < 16; j++) {
        int cout = cout0 + j;
        float bias = __ldg(&bg[cout]);
        float v0, v1, v2, v3;
        unpackf2(acc[j][0], v0, v1);
        unpackf2(acc[j][1], v2, v3);
        v0 += bias; v1 += bias; v2 += bias; v3 += bias;
        if (LAYER == 1) {
            float4* dst = reinterpret_cast<float4*>(&g_act1[(b*CC + cout)*HWW + p]);
            *dst = make_float4(v0, v1, v2, v3);
        }
        int f = cout % FF, c2 = cout / FF;
        int obase = (((LAYER*BB + b)*FF + f)*HWW + p)*2 + c2;
        out[obase]     = v0;
        out[obase + 2] = v1;
        out[obase + 4] = v2;
        out[obase + 6] = v3;
    }
}

extern "C" void kernel_launch(void* const* d_in, const int* in_sizes, int n_in,
                              void* d_out, int out_size) {
    const float* x_real = (const float*)d_in[0];
    const float* x_imag = (const float*)d_in[1];
    const float* w0r = (const float*)d_in[2];
    const float* w0i = (const float*)d_in[3];
    const float* b0r = (const float*)d_in[4];
    const float* b0i = (const float*)d_in[5];
    const float* w1r = (const float*)d_in[6];
    const float* w1i = (const float*)d_in[7];
    const float* b1r = (const float*)d_in[8];
    const float* b1i = (const float*)d_in[9];
    const float* w2r = (const float*)d_in[10];
    const float* w2i = (const float*)d_in[11];
    const float* b2r = (const float*)d_in[12];
    const float* b2i = (const float*)d_in[13];
    float* out = (float*)d_out;

    repack_small<<<(2*9*CC + 255)/256, 256>>>(w0r, w0i, b0r, b0i);
    repack_big<<<(CC*9*CC + 255)/256, 256>>>(w1r, w1i, b1r, b1i, 1);
    repack_big<<<(CC*9*CC + 255)/256, 256>>>(w2r, w2i, b2r, b2i, 2);

    conv0_kernel<<<(BB*HWW + 255)/256, 256>>>(x_real, x_imag, out);

    dim3 grid(WW/TW, HH/TH, BB);
    convL_kernel<1><<<grid, 192>>>(out);
    convL_kernel<2><<<grid, 192>>>(out);
}

// round 6
// speedup vs baseline: 1.7147x; 1.6078x over previous
#include <cuda_runtime.h>
#include <cstdint>

#define BB 2
#define FF 48
#define CC 96
#define HH 320
#define WW 320
#define HWW (HH*WW)

#define STRIP 128
#define NSTRIP (HWW/STRIP)   // 800
#define CHUNK 32
#define AP 37                 // s_a pitch (floats)
#define BP 104                // s_b pitch (floats)
#define SA_FLOATS (3*130*AP)          // 14430
#define SB_FLOATS (9*CHUNK*BP)        // 29952
#define SMEM_BYTES ((SA_FLOATS + SB_FLOATS)*4)   // 177528

// Scratch activations (pre-activation conv outputs, 96-channel real form)
__device__ float g_act0[BB*CC*HWW];
__device__ float g_act1[BB*CC*HWW];
// Repacked combined weights: layout [cin][tap][cout]
__device__ float g_w0[2*9*CC];
__device__ float g_w1[CC*9*CC];
__device__ float g_w2[CC*9*CC];
__device__ float g_b0[CC];
__device__ float g_b1[CC];
__device__ float g_b2[CC];

__device__ __forceinline__ float sigma_f(float u) {
    float quad = fmaf(u, fmaf(u, 250.0f, 0.5f), 0.00025f);
    return (fabsf(u) > 0.001f) ? fmaxf(u, 0.0f) : quad;
}

// round-to-nearest TF32; destination of cvt.*.tf32 must be a .b32 register
__device__ __forceinline__ uint32_t tf32r(float x) {
    uint32_t y;
    asm("cvt.rna.tf32.f32 %0, %1;" : "=r"(y) : "f"(x));
    return y;
}

__device__ __forceinline__ void mma_tf32(float* d, const uint32_t* a, const uint32_t* b) {
    asm("mma.sync.aligned.m16n8k8.row.col.f32.tf32.tf32.f32 "
        "{%0,%1,%2,%3}, {%4,%5,%6,%7}, {%8,%9}, {%0,%1,%2,%3};"
        : "+f"(d[0]), "+f"(d[1]), "+f"(d[2]), "+f"(d[3])
        : "r"(a[0]), "r"(a[1]), "r"(a[2]), "r"(a[3]), "r"(b[0]), "r"(b[1]));
}

// ---------------------------------------------------------------------------
// Weight repack: complex (wr, wi) -> real block [cin][tap][cout]
// ---------------------------------------------------------------------------
__global__ void repack_big(const float* __restrict__ wr, const float* __restrict__ wi,
                           const float* __restrict__ br, const float* __restrict__ bi,
                           int which) {
    float* dw = (which == 1) ? g_w1 : g_w2;
    float* db = (which == 1) ? g_b1 : g_b2;
    int idx = blockIdx.x * blockDim.x + threadIdx.x;
    if (idx < CC) db[idx] = (idx < FF) ? br[idx] : bi[idx - FF];
    if (idx >= CC*9*CC) return;
    int cout = idx % CC;
    int t    = (idx / CC) % 9;
    int cin  = idx / (9*CC);
    int fo = cout % FF, fi = cin % FF;
    const float* src = ((cout < FF) == (cin < FF)) ? wr : wi;
    float v = src[(fo*FF + fi)*9 + t];
    if (cout < FF && cin >= FF) v = -v;
    dw[idx] = v;
}

__global__ void repack_small(const float* __restrict__ wr, const float* __restrict__ wi,
                             const float* __restrict__ br, const float* __restrict__ bi) {
    int idx = blockIdx.x * blockDim.x + threadIdx.x;
    if (idx < CC) g_b0[idx] = (idx < FF) ? br[idx] : bi[idx - FF];
    if (idx >= 2*9*CC) return;
    int cout = idx % CC;
    int t    = (idx / CC) % 9;
    int cin  = idx / (9*CC);
    int fo = cout % FF;
    const float* src = ((cout < FF) == (cin == 0)) ? wr : wi;
    float v = src[fo*9 + t];
    if (cout < FF && cin == 1) v = -v;
    g_w0[idx] = v;
}

// ---------------------------------------------------------------------------
// Layer 0: conv 2 -> 96, exact fp32 (52us)
// ---------------------------------------------------------------------------
__global__ __launch_bounds__(256)
void conv0_kernel(const float* __restrict__ xr, const float* __restrict__ xi,
                  float* __restrict__ out) {
    __shared__ float sw[2*9*CC];
    __shared__ float sb[CC];
    for (int i = threadIdx.x; i < 2*9*CC; i += 256) sw[i] = g_w0[i];
    if (threadIdx.x < CC) sb[threadIdx.x] = g_b0[threadIdx.x];
    __syncthreads();

    int pix = blockIdx.x * 256 + threadIdx.x;
    if (pix >= BB*HWW) return;
    int b = pix / HWW;
    int p = pix - b*HWW;
    int y = p / WW, x = p - y*WW;

    const float* x0 = xr + b*HWW;
    const float* x1 = xi + b*HWW;
    float in[18];
    #pragma unroll
    for (int dy = 0; dy < 3; dy++) {
        #pragma unroll
        for (int dx = 0; dx < 3; dx++) {
            int yy = y + dy - 1, xx = x + dx - 1;
            bool ok = (yy >= 0) && (yy < HH) && (xx >= 0) && (xx < WW);
            in[dy*3 + dx]     = ok ? x0[yy*WW + xx] : 0.0f;
            in[9 + dy*3 + dx] = ok ? x1[yy*WW + xx] : 0.0f;
        }
    }

    #pragma unroll 4
    for (int cout = 0; cout < CC; cout++) {
        float acc = sb[cout];
        #pragma unroll
        for (int t = 0; t < 18; t++)
            acc = fmaf(in[t], sw[t*CC + cout], acc);
        g_act0[(b*CC + cout)*HWW + p] = acc;
        int f = cout % FF, c2 = cout / FF;
        out[((b*FF + f)*HWW + p)*2 + c2] = acc;
    }
}

// ---------------------------------------------------------------------------
// Layers 1,2 bulk: TF32 tensor-core implicit GEMM over flat 128-pixel strips.
// Block 256 thr = 8 warps (4M x 2N): warp = 32 px x 48 couts.
// Row-wrap at x=0/319 produces wrong values there; fixup kernel repairs.
// ---------------------------------------------------------------------------
template<int LAYER>
__global__ __launch_bounds__(256, 1)
void convT_kernel(float* __restrict__ out) {
    extern __shared__ float smem[];
    float* s_a = smem;              // [dy3][px130][cin32] pitch AP
    float* s_b = smem + SA_FLOATS;  // [tap9][k32][cout96] pitch BP

    const float* __restrict__ act_in = (LAYER == 1) ? g_act0 : g_act1;
    const float* __restrict__ wg     = (LAYER == 1) ? g_w1 : g_w2;
    const float* __restrict__ bg     = (LAYER == 1) ? g_b1 : g_b2;

    int strip = blockIdx.x;
    int b     = blockIdx.y;
    int base  = strip * STRIP;
    int tid   = threadIdx.x;
    int warp  = tid >> 5, lane = tid & 31;
    int m0 = (warp >> 1) * 32;
    int n0 = (warp & 1) * 48;
    int gid = lane >> 2, qid = lane & 3;

    float acc[2][6][4];
    #pragma unroll
    for (int h = 0; h < 2; h++)
        #pragma unroll
        for (int nt = 0; nt < 6; nt++)
            #pragma unroll
            for (int r = 0; r < 4; r++) acc[h][nt][r] = 0.0f;

    for (int c0 = 0; c0 < CC; c0 += CHUNK) {
        // --- stage A: sigma + tf32-round, 3 halo rows x 130 px x 32 cin ---
        for (int i = tid; i < CHUNK*3*130; i += 256) {
            int c   = i / 390;
            int rem = i - c*390;
            int dy  = rem / 130;
            int px  = rem - dy*130;
            int fl  = base + (dy - 1)*WW + px - 1;
            uint32_t v = 0u;
            if (fl >= 0 && fl < HWW)
                v = tf32r(sigma_f(act_in[(b*CC + c0 + c)*HWW + fl]));
            s_a[(dy*130 + px)*AP + c] = __uint_as_float(v);
        }
        // --- stage B: all 9 taps x 32 cin x 96 couts, tf32-round ---
        const float* wsrc = wg + c0*9*CC;
        for (int i = tid; i < CHUNK*9*CC; i += 256) {
            int k   = i / (9*CC);
            int rem = i - k*9*CC;
            int tap = rem / CC;
            int n   = rem - tap*CC;
            s_b[(tap*CHUNK + k)*BP + n] = __uint_as_float(tf32r(wsrc[i]));
        }
        __syncthreads();

        #pragma unroll
        for (int tap = 0; tap < 9; tap++) {
            int dy = tap / 3, dx = tap - dy*3;
            const float* sa_base = s_a + (dy*130 + dx)*AP;  // element (m,c): sa_base[m*AP + c]
            #pragma unroll
            for (int kk = 0; kk < CHUNK; kk += 8) {
                uint32_t a[2][4];
                #pragma unroll
                for (int h = 0; h < 2; h++) {
                    const float* ap = sa_base + (m0 + h*16 + gid)*AP + kk + qid;
                    a[h][0] = __float_as_uint(ap[0]);
                    a[h][1] = __float_as_uint(ap[8*AP]);
                    a[h][2] = __float_as_uint(ap[4]);
                    a[h][3] = __float_as_uint(ap[8*AP + 4]);
                }
                uint32_t bf[6][2];
                const float* sb_base = s_b + (tap*CHUNK + kk)*BP;
                #pragma unroll
                for (int nt = 0; nt < 6; nt++) {
                    const float* bp = sb_base + qid*BP + n0 + nt*8 + gid;
                    bf[nt][0] = __float_as_uint(bp[0]);
                    bf[nt][1] = __float_as_uint(bp[4*BP]);
                }
                #pragma unroll
                for (int h = 0; h < 2; h++)
                    #pragma unroll
                    for (int nt = 0; nt < 6; nt++)
                        mma_tf32(acc[h][nt], a[h], bf[nt]);
            }
        }
        __syncthreads();
    }

    // --- epilogue: frags -> smem transpose -> coalesced stores ---
    float* s_o = smem;  // [cout96][px] pitch 130
    #pragma unroll
    for (int h = 0; h < 2; h++)
        #pragma unroll
        for (int nt = 0; nt < 6; nt++) {
            int m = m0 + h*16 + gid;
            int n = n0 + nt*8 + 2*qid;
            s_o[n*130 + m]           = acc[h][nt][0];
            s_o[(n+1)*130 + m]       = acc[h][nt][1];
            s_o[n*130 + m + 8]       = acc[h][nt][2];
            s_o[(n+1)*130 + m + 8]   = acc[h][nt][3];
        }
    __syncthreads();

    for (int i = tid; i < FF*STRIP; i += 256) {
        int f  = i >> 7;
        int px = i & (STRIP-1);
        float v0 = s_o[f*130 + px]        + bg[f];
        float v1 = s_o[(f+FF)*130 + px]   + bg[f+FF];
        if (LAYER == 1) {
            g_act1[(b*CC + f)*HWW + base + px]      = v0;
            g_act1[(b*CC + f+FF)*HWW + base + px]   = v1;
        }
        reinterpret_cast<float2*>(out)[((size_t)(LAYER*BB + b)*FF + f)*HWW + base + px]
            = make_float2(v0, v1);
    }
}

// ---------------------------------------------------------------------------
// Border fixup: exact fp32 recompute of columns x=0 and x=319 for layer L.
// Block = 96 threads (one per cout); grid = BB*HH*2.
// ---------------------------------------------------------------------------
template<int LAYER>
__global__ __launch_bounds__(96)
void fixup_kernel(float* __restrict__ out) {
    const float* __restrict__ act_in = (LAYER == 1) ? g_act0 : g_act1;
    const float* __restrict__ wg     = (LAYER == 1) ? g_w1 : g_w2;
    const float* __restrict__ bg     = (LAYER == 1) ? g_b1 : g_b2;

    int blk  = blockIdx.x;
    int side = blk & 1;
    int y    = (blk >> 1) % HH;
    int b    = (blk >> 1) / HH;
    int x    = side ? (WW-1) : 0;
    int xs   = side ? (WW-2) : 0;     // base of the 2 valid columns
    int cout = threadIdx.x;

    __shared__ float s_act[3][2][CC];
    for (int i = cout; i < 3*2*CC; i += 96) {
        int c   = i % CC;
        int dxl = (i / CC) % 2;
        int dy  = i / (2*CC);
        int yy  = y + dy - 1;
        float v = 0.0f;
        if (yy >= 0 && yy < HH)
            v = sigma_f(act_in[(b*CC + c)*HWW + yy*WW + xs + dxl]);
        s_act[dy][dxl][c] = v;
    }
    __syncthreads();

    float acc = bg[cout];
    #pragma unroll
    for (int dy = 0; dy < 3; dy++)
        #pragma unroll
        for (int dx = 0; dx < 3; dx++) {
            int xx = x + dx - 1;
            if (xx < 0 || xx >= WW) continue;
            int dxl = xx - xs;
            const float* wp = wg + (dy*3 + dx)*CC + cout;
            for (int c = 0; c < CC; c++)
                acc = fmaf(wp[c*9*CC], s_act[dy][dxl][c], acc);
        }

    int p = y*WW + x;
    if (LAYER == 1) g_act1[(b*CC + cout)*HWW + p] = acc;
    int f = cout % FF, c2 = cout / FF;
    out[(((LAYER*BB + b)*FF + f)*HWW + p)*2 + c2] = acc;
}

extern "C" void kernel_launch(void* const* d_in, const int* in_sizes, int n_in,
                              void* d_out, int out_size) {
    const float* x_real = (const float*)d_in[0];
    const float* x_imag = (const float*)d_in[1];
    const float* w0r = (const float*)d_in[2];
    const float* w0i = (const float*)d_in[3];
    const float* b0r = (const float*)d_in[4];
    const float* b0i = (const float*)d_in[5];
    const float* w1r = (const float*)d_in[6];
    const float* w1i = (const float*)d_in[7];
    const float* b1r = (const float*)d_in[8];
    const float* b1i = (const float*)d_in[9];
    const float* w2r = (const float*)d_in[10];
    const float* w2i = (const float*)d_in[11];
    const float* b2r = (const float*)d_in[12];
    const float* b2i = (const float*)d_in[13];
    float* out = (float*)d_out;

    static bool attr_set = false;
    if (!attr_set) {
        cudaFuncSetAttribute(convT_kernel<1>, cudaFuncAttributeMaxDynamicSharedMemorySize, SMEM_BYTES);
        cudaFuncSetAttribute(convT_kernel<2>, cudaFuncAttributeMaxDynamicSharedMemorySize, SMEM_BYTES);
        attr_set = true;
    }

    repack_small<<<(2*9*CC + 255)/256, 256>>>(w0r, w0i, b0r, b0i);
    repack_big<<<(CC*9*CC + 255)/256, 256>>>(w1r, w1i, b1r, b1i, 1);
    repack_big<<<(CC*9*CC + 255)/256, 256>>>(w2r, w2i, b2r, b2i, 2);

    conv0_kernel<<<(BB*HWW + 255)/256, 256>>>(x_real, x_imag, out);

    dim3 grid(NSTRIP, BB);
    convT_kernel<1><<<grid, 256, SMEM_BYTES>>>(out);
    fixup_kernel<1><<<BB*HH*2, 96>>>(out);
    convT_kernel<2><<<grid, 256, SMEM_BYTES>>>(out);
    fixup_kernel<2><<<BB*HH*2, 96>>>(out);
}

// round 7
// speedup vs baseline: 3.5212x; 2.0536x over previous
#include <cuda_runtime.h>
#include <cstdint>

#define BB 2
#define FF 48
#define CC 96
#define HH 320
#define WW 320
#define HWW (HH*WW)

#define STRIP 128
#define NSTRIP (HWW/STRIP)   // 800
#define CHUNK 16
#define NCH (CC/CHUNK)       // 6
#define AROW 136             // floats per (c,dy) smem row (4-aligned, +3 lead pad)
#define ACST (3*AROW)        // 408: stride per input channel in s_a
#define BP 104               // s_b cout pitch (conflict-free qid*104%32=8)
#define SA_FLOATS (CHUNK*ACST)        // 6528
#define SB_FLOATS (9*CHUNK*BP)        // 14976  (= one weight chunk image)
#define SMEM_BYTES ((SA_FLOATS + SB_FLOATS)*4)   // 86016 -> 2 CTAs/SM

// sigma+tf32 pre-activations (inputs to convT layers)
__device__ float g_sig0[BB*CC*HWW];
__device__ float g_sig1[BB*CC*HWW];
// weights: tf32-pre-rounded, pre-padded chunk images [chunk][tap][k16][cout104]
__device__ float g_w0[2*9*CC];
__device__ float g_w1[NCH*SB_FLOATS];
__device__ float g_w2[NCH*SB_FLOATS];
__device__ float g_b0[CC];
__device__ float g_b1[CC];
__device__ float g_b2[CC];

__device__ __forceinline__ float sigma_f(float u) {
    float quad = fmaf(u, fmaf(u, 250.0f, 0.5f), 0.00025f);
    return (fabsf(u) > 0.001f) ? fmaxf(u, 0.0f) : quad;
}

__device__ __forceinline__ uint32_t tf32r(float x) {
    uint32_t y;
    asm("cvt.rna.tf32.f32 %0, %1;" : "=r"(y) : "f"(x));
    return y;
}

__device__ __forceinline__ void mma_tf32(float* d, const uint32_t* a, const uint32_t* b) {
    asm("mma.sync.aligned.m16n8k8.row.col.f32.tf32.tf32.f32 "
        "{%0,%1,%2,%3}, {%4,%5,%6,%7}, {%8,%9}, {%0,%1,%2,%3};"
        : "+f"(d[0]), "+f"(d[1]), "+f"(d[2]), "+f"(d[3])
        : "r"(a[0]), "r"(a[1]), "r"(a[2]), "r"(a[3]), "r"(b[0]), "r"(b[1]));
}

// ---------------------------------------------------------------------------
// Weight repack: complex (wr, wi) -> tf32-rounded padded chunk image
// value(cout,cin): [[wr,-wi],[wi,wr]] block structure
// ---------------------------------------------------------------------------
__global__ void repack_big(const float* __restrict__ wr, const float* __restrict__ wi,
                           const float* __restrict__ br, const float* __restrict__ bi,
                           int which) {
    float* dw = (which == 1) ? g_w1 : g_w2;
    float* db = (which == 1) ? g_b1 : g_b2;
    int idx = blockIdx.x * blockDim.x + threadIdx.x;
    if (idx < CC) db[idx] = (idx < FF) ? br[idx] : bi[idx - FF];
    if (idx >= CC*9*CC) return;
    int cout = idx % CC;
    int t    = (idx / CC) % 9;
    int cin  = idx / (9*CC);
    int fo = cout % FF, fi = cin % FF;
    const float* src = ((cout < FF) == (cin < FF)) ? wr : wi;
    float v = src[(fo*FF + fi)*9 + t];
    if (cout < FF && cin >= FF) v = -v;
    int ci = cin / CHUNK, k = cin % CHUNK;
    dw[((ci*9 + t)*CHUNK + k)*BP + cout] = __uint_as_float(tf32r(v));
}

__global__ void repack_small(const float* __restrict__ wr, const float* __restrict__ wi,
                             const float* __restrict__ br, const float* __restrict__ bi) {
    int idx = blockIdx.x * blockDim.x + threadIdx.x;
    if (idx < CC) g_b0[idx] = (idx < FF) ? br[idx] : bi[idx - FF];
    if (idx >= 2*9*CC) return;
    int cout = idx % CC;
    int t    = (idx / CC) % 9;
    int cin  = idx / (9*CC);
    int fo = cout % FF;
    const float* src = ((cout < FF) == (cin == 0)) ? wr : wi;
    float v = src[fo*9 + t];
    if (cout < FF && cin == 1) v = -v;
    g_w0[idx] = v;
}

// ---------------------------------------------------------------------------
// Layer 0: conv 2 -> 96, exact fp32; writes out + g_sig0 = tf32(sigma(.))
// ---------------------------------------------------------------------------
__global__ __launch_bounds__(256)
void conv0_kernel(const float* __restrict__ xr, const float* __restrict__ xi,
                  float* __restrict__ out) {
    __shared__ float sw[2*9*CC];
    __shared__ float sb[CC];
    for (int i = threadIdx.x; i < 2*9*CC; i += 256) sw[i] = g_w0[i];
    if (threadIdx.x < CC) sb[threadIdx.x] = g_b0[threadIdx.x];
    __syncthreads();

    int pix = blockIdx.x * 256 + threadIdx.x;
    if (pix >= BB*HWW) return;
    int b = pix / HWW;
    int p = pix - b*HWW;
    int y = p / WW, x = p - y*WW;

    const float* x0 = xr + b*HWW;
    const float* x1 = xi + b*HWW;
    float in[18];
    #pragma unroll
    for (int dy = 0; dy < 3; dy++) {
        #pragma unroll
        for (int dx = 0; dx < 3; dx++) {
            int yy = y + dy - 1, xx = x + dx - 1;
            bool ok = (yy >= 0) && (yy < HH) && (xx >= 0) && (xx < WW);
            in[dy*3 + dx]     = ok ? x0[yy*WW + xx] : 0.0f;
            in[9 + dy*3 + dx] = ok ? x1[yy*WW + xx] : 0.0f;
        }
    }

    #pragma unroll 4
    for (int cout = 0; cout < CC; cout++) {
        float acc = sb[cout];
        #pragma unroll
        for (int t = 0; t < 18; t++)
            acc = fmaf(in[t], sw[t*CC + cout], acc);
        g_sig0[(b*CC + cout)*HWW + p] = __uint_as_float(tf32r(sigma_f(acc)));
        int f = cout % FF, c2 = cout / FF;
        out[((b*FF + f)*HWW + p)*2 + c2] = acc;
    }
}

// ---------------------------------------------------------------------------
// Layers 1,2 bulk: TF32 m16n8k8 implicit GEMM over flat 128-pixel strips.
// Block 256 thr = 8 warps (4M x 2N), 2 CTAs/SM (84KB smem).
// A staging: pure float4 copy of pre-sigma'd input (slow path only at image
// top/bottom boundary CTAs, which also provides exact y-padding zeros).
// B staging: pure float4 memcpy of pre-rounded padded weight chunk image.
// Row-wrap at x=0/319 wrong by construction -> fixup kernel repairs.
// ---------------------------------------------------------------------------
template<int LAYER>
__global__ __launch_bounds__(256, 2)
void convT_kernel(float* __restrict__ out) {
    extern __shared__ float smem[];
    float* s_a = smem;              // [c16][dy3][136]
    float* s_b = smem + SA_FLOATS;  // [tap9][k16][104]

    const float* __restrict__ sig_in = (LAYER == 1) ? g_sig0 : g_sig1;
    const float* __restrict__ wg     = (LAYER == 1) ? g_w1 : g_w2;
    const float* __restrict__ bg     = (LAYER == 1) ? g_b1 : g_b2;

    int strip = blockIdx.x;
    int b     = blockIdx.y;
    int base  = strip * STRIP;
    int tid   = threadIdx.x;
    int warp  = tid >> 5, lane = tid & 31;
    int m0 = (warp >> 1) * 32;
    int n0 = (warp & 1) * 48;
    int gid = lane >> 2, qid = lane & 3;

    float acc[2][6][4];
    #pragma unroll
    for (int h = 0; h < 2; h++)
        #pragma unroll
        for (int nt = 0; nt < 6; nt++)
            #pragma unroll
            for (int r = 0; r < 4; r++) acc[h][nt][r] = 0.0f;

    for (int ci = 0; ci < NCH; ci++) {
        int c0 = ci * CHUNK;
        // --- stage A: 48 rows of 34 float4 each ---
        for (int i = tid; i < CHUNK*3*34; i += 256) {
            int row = i / 34, j = i - row*34;
            int c = row / 3, dy = row - c*3;
            const float* ch = sig_in + (size_t)(b*CC + c0 + c)*HWW;
            int fl0m3 = base + (dy - 1)*WW - 4;   // fl0-3, 16B aligned
            int e0 = fl0m3 + 4*j;
            float4 v;
            if (fl0m3 >= 0 && fl0m3 + 135 < HWW) {
                v = *(const float4*)(ch + e0);
            } else {
                v.x = (e0   >= 0 && e0   < HWW) ? ch[e0]   : 0.0f;
                v.y = (e0+1 >= 0 && e0+1 < HWW) ? ch[e0+1] : 0.0f;
                v.z = (e0+2 >= 0 && e0+2 < HWW) ? ch[e0+2] : 0.0f;
                v.w = (e0+3 >= 0 && e0+3 < HWW) ? ch[e0+3] : 0.0f;
            }
            *(float4*)(s_a + c*ACST + dy*AROW + 4*j) = v;
        }
        // --- stage B: straight 16B memcpy of chunk image ---
        const float4* wc = (const float4*)(wg + (size_t)ci*SB_FLOATS);
        float4* sb4 = (float4*)s_b;
        for (int i = tid; i < SB_FLOATS/4; i += 256) sb4[i] = wc[i];
        __syncthreads();

        #pragma unroll
        for (int tap = 0; tap < 9; tap++) {
            int dy = tap / 3, dx = tap - dy*3;
            #pragma unroll
            for (int kk = 0; kk < CHUNK; kk += 8) {
                uint32_t a[2][4];
                #pragma unroll
                for (int h = 0; h < 2; h++) {
                    const float* ap = s_a + (kk + qid)*ACST + dy*AROW + 3 + dx
                                          + m0 + h*16 + gid;
                    a[h][0] = __float_as_uint(ap[0]);
                    a[h][1] = __float_as_uint(ap[8]);
                    a[h][2] = __float_as_uint(ap[4*ACST]);
                    a[h][3] = __float_as_uint(ap[4*ACST + 8]);
                }
                uint32_t bf[6][2];
                const float* sbb = s_b + (tap*CHUNK + kk + qid)*BP;
                #pragma unroll
                for (int nt = 0; nt < 6; nt++) {
                    const float* bp = sbb + n0 + nt*8 + gid;
                    bf[nt][0] = __float_as_uint(bp[0]);
                    bf[nt][1] = __float_as_uint(bp[4*BP]);
                }
                #pragma unroll
                for (int h = 0; h < 2; h++)
                    #pragma unroll
                    for (int nt = 0; nt < 6; nt++)
                        mma_tf32(acc[h][nt], a[h], bf[nt]);
            }
        }
        __syncthreads();
    }

    // --- epilogue: frags -> smem transpose -> coalesced stores ---
    float* s_o = smem;  // [cout96][px] pitch 130
    #pragma unroll
    for (int h = 0; h < 2; h++)
        #pragma unroll
        for (int nt = 0; nt < 6; nt++) {
            int m = m0 + h*16 + gid;
            int n = n0 + nt*8 + 2*qid;
            s_o[n*130 + m]           = acc[h][nt][0];
            s_o[(n+1)*130 + m]       = acc[h][nt][1];
            s_o[n*130 + m + 8]       = acc[h][nt][2];
            s_o[(n+1)*130 + m + 8]   = acc[h][nt][3];
        }
    __syncthreads();

    for (int i = tid; i < FF*STRIP; i += 256) {
        int f  = i >> 7;
        int px = i & (STRIP-1);
        float v0 = s_o[f*130 + px]        + bg[f];
        float v1 = s_o[(f+FF)*130 + px]   + bg[f+FF];
        if (LAYER == 1) {
            g_sig1[(b*CC + f)*HWW + base + px]
                = __uint_as_float(tf32r(sigma_f(v0)));
            g_sig1[(b*CC + f+FF)*HWW + base + px]
                = __uint_as_float(tf32r(sigma_f(v1)));
        }
        reinterpret_cast<float2*>(out)[((size_t)(LAYER*BB + b)*FF + f)*HWW + base + px]
            = make_float2(v0, v1);
    }
}

// ---------------------------------------------------------------------------
// Border fixup: recompute columns x=0 and x=319 for layer L (x-wrap repair).
// Reads pre-sigma'd inputs; writes out (+ g_sig1 for L=1).
// ---------------------------------------------------------------------------
template<int LAYER>
__global__ __launch_bounds__(96)
void fixup_kernel(float* __restrict__ out) {
    const float* __restrict__ sig_in = (LAYER == 1) ? g_sig0 : g_sig1;
    const float* __restrict__ wg     = (LAYER == 1) ? g_w1 : g_w2;
    const float* __restrict__ bg     = (LAYER == 1) ? g_b1 : g_b2;

    int blk  = blockIdx.x;
    int side = blk & 1;
    int y    = (blk >> 1) % HH;
    int b    = (blk >> 1) / HH;
    int x    = side ? (WW-1) : 0;
    int xs   = side ? (WW-2) : 0;
    int cout = threadIdx.x;

    __shared__ float s_act[3][2][CC];
    for (int i = cout; i < 3*2*CC; i += 96) {
        int c   = i % CC;
        int dxl = (i / CC) % 2;
        int dy  = i / (2*CC);
        int yy  = y + dy - 1;
        float v = 0.0f;
        if (yy >= 0 && yy < HH)
            v = sig_in[(b*CC + c)*HWW + yy*WW + xs + dxl];
        s_act[dy][dxl][c] = v;
    }
    __syncthreads();

    float acc = bg[cout];
    #pragma unroll
    for (int dy = 0; dy < 3; dy++)
        #pragma unroll
        for (int dx = 0; dx < 3; dx++) {
            int xx = x + dx - 1;
            if (xx < 0 || xx >= WW) continue;
            int dxl = xx - xs;
            for (int c = 0; c < CC; c++) {
                float w = wg[(((c/CHUNK)*9 + dy*3 + dx)*CHUNK + (c%CHUNK))*BP + cout];
                acc = fmaf(w, s_act[dy][dxl][c], acc);
            }
        }

    int p = y*WW + x;
    if (LAYER == 1)
        g_sig1[(b*CC + cout)*HWW + p] = __uint_as_float(tf32r(sigma_f(acc)));
    int f = cout % FF, c2 = cout / FF;
    out[(((LAYER*BB + b)*FF + f)*HWW + p)*2 + c2] = acc;
}

extern "C" void kernel_launch(void* const* d_in, const int* in_sizes, int n_in,
                              void* d_out, int out_size) {
    const float* x_real = (const float*)d_in[0];
    const float* x_imag = (const float*)d_in[1];
    const float* w0r = (const float*)d_in[2];
    const float* w0i = (const float*)d_in[3];
    const float* b0r = (const float*)d_in[4];
    const float* b0i = (const float*)d_in[5];
    const float* w1r = (const float*)d_in[6];
    const float* w1i = (const float*)d_in[7];
    const float* b1r = (const float*)d_in[8];
    const float* b1i = (const float*)d_in[9];
    const float* w2r = (const float*)d_in[10];
    const float* w2i = (const float*)d_in[11];
    const float* b2r = (const float*)d_in[12];
    const float* b2i = (const float*)d_in[13];
    float* out = (float*)d_out;

    static bool attr_set = false;
    if (!attr_set) {
        cudaFuncSetAttribute(convT_kernel<1>, cudaFuncAttributeMaxDynamicSharedMemorySize, SMEM_BYTES);
        cudaFuncSetAttribute(convT_kernel<2>, cudaFuncAttributeMaxDynamicSharedMemorySize, SMEM_BYTES);
        attr_set = true;
    }

    repack_small<<<(2*9*CC + 255)/256, 256>>>(w0r, w0i, b0r, b0i);
    repack_big<<<(CC*9*CC + 255)/256, 256>>>(w1r, w1i, b1r, b1i, 1);
    repack_big<<<(CC*9*CC + 255)/256, 256>>>(w2r, w2i, b2r, b2i, 2);

    conv0_kernel<<<(BB*HWW + 255)/256, 256>>>(x_real, x_imag, out);

    dim3 grid(NSTRIP, BB);
    convT_kernel<1><<<grid, 256, SMEM_BYTES>>>(out);
    fixup_kernel<1><<<BB*HH*2, 96>>>(out);
    convT_kernel<2><<<grid, 256, SMEM_BYTES>>>(out);
    fixup_kernel<2><<<BB*HH*2, 96>>>(out);
}

// round 8
// speedup vs baseline: 5.0331x; 1.4294x over previous
#include <cuda_runtime.h>
#include <cuda_fp16.h>
#include <cstdint>

#define BB 2
#define FF 48
#define CC 96
#define HH 320
#define WW 320
#define HWW (HH*WW)

#define STRIP 128
#define NSTRIP (HWW/STRIP)   // 800
#define CHUNK 16
#define NCH (CC/CHUNK)       // 6
#define APX 24               // halfs per pixel row in s_a (16 data + 8 pad; 48B, 16B-aligned)
#define BPX 24               // halfs per cout row in s_b (16 data + 8 pad)
#define SA_HALFS (3*130*APX)          // 9360
#define SB_HALFS (9*CC*BPX)           // 20736 (one weight chunk image)
#define SMEM_BYTES ((SA_HALFS + SB_HALFS)*2)   // 60192 -> 2 CTAs/SM

// sigma'd activations, fp16, pixel-interleaved by 16-ch chunk: [b][ci][pix][k16]
__device__ __half g_sig0[(size_t)BB*NCH*HWW*CHUNK];
__device__ __half g_sig1[(size_t)BB*NCH*HWW*CHUNK];
// weights: fp16 pre-rounded padded chunk images [ci][tap][cout][BPX]
__device__ float  g_w0[2*9*CC];
__device__ __half g_w1[NCH*SB_HALFS];
__device__ __half g_w2[NCH*SB_HALFS];
__device__ float g_b0[CC];
__device__ float g_b1[CC];
__device__ float g_b2[CC];

__device__ __forceinline__ float sigma_f(float u) {
    float quad = fmaf(u, fmaf(u, 250.0f, 0.5f), 0.00025f);
    return (fabsf(u) > 0.001f) ? fmaxf(u, 0.0f) : quad;
}

__device__ __forceinline__ void mma_f16(float* d, const uint32_t* a, const uint32_t* b) {
    asm("mma.sync.aligned.m16n8k16.row.col.f32.f16.f16.f32 "
        "{%0,%1,%2,%3}, {%4,%5,%6,%7}, {%8,%9}, {%0,%1,%2,%3};"
        : "+f"(d[0]), "+f"(d[1]), "+f"(d[2]), "+f"(d[3])
        : "r"(a[0]), "r"(a[1]), "r"(a[2]), "r"(a[3]), "r"(b[0]), "r"(b[1]));
}

__device__ __forceinline__ void ldmA(uint32_t* r, const __half* p) {
    uint32_t addr = (uint32_t)__cvta_generic_to_shared(p);
    asm volatile("ldmatrix.sync.aligned.m8n8.x4.shared.b16 {%0,%1,%2,%3}, [%4];"
        : "=r"(r[0]), "=r"(r[1]), "=r"(r[2]), "=r"(r[3]) : "r"(addr));
}

// ---------------------------------------------------------------------------
// Weight repack: complex (wr, wi) -> fp16 padded chunk image [ci][tap][cout][BPX]
// ---------------------------------------------------------------------------
__global__ void repack_big(const float* __restrict__ wr, const float* __restrict__ wi,
                           const float* __restrict__ br, const float* __restrict__ bi,
                           int which) {
    __half* dw = (which == 1) ? g_w1 : g_w2;
    float*  db = (which == 1) ? g_b1 : g_b2;
    int idx = blockIdx.x * blockDim.x + threadIdx.x;
    if (idx < CC) db[idx] = (idx < FF) ? br[idx] : bi[idx - FF];
    if (idx >= NCH*9*CC*BPX) return;
    int k    = idx % BPX;
    int cout = (idx / BPX) % CC;
    int t    = (idx / (BPX*CC)) % 9;
    int ci   = idx / (BPX*CC*9);
    float v = 0.0f;
    if (k < CHUNK) {
        int cin = ci*CHUNK + k;
        int fo = cout % FF, fi = cin % FF;
        const float* src = ((cout < FF) == (cin < FF)) ? wr : wi;
        v = src[(fo*FF + fi)*9 + t];
        if (cout < FF && cin >= FF) v = -v;
    }
    dw[idx] = __float2half_rn(v);
}

__global__ void repack_small(const float* __restrict__ wr, const float* __restrict__ wi,
                             const float* __restrict__ br, const float* __restrict__ bi) {
    int idx = blockIdx.x * blockDim.x + threadIdx.x;
    if (idx < CC) g_b0[idx] = (idx < FF) ? br[idx] : bi[idx - FF];
    if (idx >= 2*9*CC) return;
    int cout = idx % CC;
    int t    = (idx / CC) % 9;
    int cin  = idx / (9*CC);
    int fo = cout % FF;
    const float* src = ((cout < FF) == (cin == 0)) ? wr : wi;
    float v = src[fo*9 + t];
    if (cout < FF && cin == 1) v = -v;
    g_w0[idx] = v;
}

// ---------------------------------------------------------------------------
// Layer 0: conv 2 -> 96, exact fp32; writes out + g_sig0 (half, interleaved)
// ---------------------------------------------------------------------------
__global__ __launch_bounds__(256)
void conv0_kernel(const float* __restrict__ xr, const float* __restrict__ xi,
                  float* __restrict__ out) {
    __shared__ float sw[2*9*CC];
    __shared__ float sb[CC];
    for (int i = threadIdx.x; i < 2*9*CC; i += 256) sw[i] = g_w0[i];
    if (threadIdx.x < CC) sb[threadIdx.x] = g_b0[threadIdx.x];
    __syncthreads();

    int pix = blockIdx.x * 256 + threadIdx.x;
    if (pix >= BB*HWW) return;
    int b = pix / HWW;
    int p = pix - b*HWW;
    int y = p / WW, x = p - y*WW;

    const float* x0 = xr + b*HWW;
    const float* x1 = xi + b*HWW;
    float in[18];
    #pragma unroll
    for (int dy = 0; dy < 3; dy++) {
        #pragma unroll
        for (int dx = 0; dx < 3; dx++) {
            int yy = y + dy - 1, xx = x + dx - 1;
            bool ok = (yy >= 0) && (yy < HH) && (xx >= 0) && (xx < WW);
            in[dy*3 + dx]     = ok ? x0[yy*WW + xx] : 0.0f;
            in[9 + dy*3 + dx] = ok ? x1[yy*WW + xx] : 0.0f;
        }
    }

    for (int ci = 0; ci < NCH; ci++) {
        uint32_t u[8];
        #pragma unroll
        for (int j2 = 0; j2 < 8; j2++) {
            float a2[2];
            #pragma unroll
            for (int s = 0; s < 2; s++) {
                int cout = ci*CHUNK + 2*j2 + s;
                float acc = sb[cout];
                #pragma unroll
                for (int t = 0; t < 18; t++)
                    acc = fmaf(in[t], sw[t*CC + cout], acc);
                int f = cout % FF, c2 = cout / FF;
                out[((b*FF + f)*HWW + p)*2 + c2] = acc;
                a2[s] = sigma_f(acc);
            }
            __half2 hh = __floats2half2_rn(a2[0], a2[1]);
            u[j2] = *reinterpret_cast<uint32_t*>(&hh);
        }
        uint4* dst = reinterpret_cast<uint4*>(
            g_sig0 + ((size_t)(b*NCH + ci)*HWW + p)*CHUNK);
        dst[0] = make_uint4(u[0], u[1], u[2], u[3]);
        dst[1] = make_uint4(u[4], u[5], u[6], u[7]);
    }
}

// ---------------------------------------------------------------------------
// Layers 1,2 bulk: fp16 m16n8k16 implicit GEMM over flat 128-pixel strips.
// Block 256 thr = 8 warps (4M x 2N), 2 CTAs/SM (~60KB smem).
// A staging: uint4 copy of pre-sigma'd interleaved halfs (zeros at y-bounds).
// B staging: flat memcpy of padded fp16 weight chunk image.
// Row-wrap at x=0/319 wrong by construction -> fixup repairs.
// ---------------------------------------------------------------------------
template<int LAYER>
__global__ __launch_bounds__(256, 2)
void convT_kernel(float* __restrict__ out) {
    extern __shared__ __align__(16) char smem_raw[];
    __half* s_a = reinterpret_cast<__half*>(smem_raw);        // [dy3][px130][APX]
    __half* s_b = s_a + SA_HALFS;                             // [tap9][cout96][BPX]

    const __half* __restrict__ sig_in = (LAYER == 1) ? g_sig0 : g_sig1;
    const __half* __restrict__ wg     = (LAYER == 1) ? g_w1 : g_w2;
    const float*  __restrict__ bg     = (LAYER == 1) ? g_b1 : g_b2;

    int strip = blockIdx.x;
    int b     = blockIdx.y;
    int base  = strip * STRIP;
    int tid   = threadIdx.x;
    int warp  = tid >> 5, lane = tid & 31;
    int m0 = (warp >> 1) * 32;
    int n0 = (warp & 1) * 48;
    int gid = lane >> 2, qid = lane & 3;
    int arow = lane & 15, akoff = (lane >> 4) * 8;

    float acc[2][6][4];
    #pragma unroll
    for (int h = 0; h < 2; h++)
        #pragma unroll
        for (int nt = 0; nt < 6; nt++)
            #pragma unroll
            for (int r = 0; r < 4; r++) acc[h][nt][r] = 0.0f;

    for (int ci = 0; ci < NCH; ci++) {
        // --- stage A: 3 x 130 pixel-blocks of 32B (2 uint4 each) ---
        const __half* plane = sig_in + (size_t)(b*NCH + ci)*HWW*CHUNK;
        for (int i = tid; i < 2*3*130; i += 256) {
            int blk = i >> 1, hi = i & 1;
            int dyr = blk / 130, px = blk - dyr*130;
            int fl  = base + (dyr - 1)*WW + px - 1;
            uint4 v = make_uint4(0u, 0u, 0u, 0u);
            if (fl >= 0 && fl < HWW)
                v = reinterpret_cast<const uint4*>(plane + (size_t)fl*CHUNK)[hi];
            reinterpret_cast<uint4*>(s_a + (dyr*130 + px)*APX)[hi] = v;
        }
        // --- stage B: straight 16B memcpy of chunk image ---
        const uint4* wc = reinterpret_cast<const uint4*>(wg + (size_t)ci*SB_HALFS);
        uint4* sb4 = reinterpret_cast<uint4*>(s_b);
        for (int i = tid; i < SB_HALFS/8; i += 256) sb4[i] = wc[i];
        __syncthreads();

        #pragma unroll
        for (int tap = 0; tap < 9; tap++) {
            int dy = tap / 3, dx = tap - dy*3;
            uint32_t bf[6][2];
            const __half* sbb = s_b + tap*CC*BPX;
            #pragma unroll
            for (int nt = 0; nt < 6; nt++) {
                const __half* bp = sbb + (n0 + nt*8 + gid)*BPX + 2*qid;
                bf[nt][0] = *reinterpret_cast<const uint32_t*>(bp);
                bf[nt][1] = *reinterpret_cast<const uint32_t*>(bp + 8);
            }
            #pragma unroll
            for (int h = 0; h < 2; h++) {
                uint32_t a[4];
                const __half* ap = s_a + (dy*130 + dx + m0 + h*16 + arow)*APX + akoff;
                ldmA(a, ap);
                #pragma unroll
                for (int nt = 0; nt < 6; nt++)
                    mma_f16(acc[h][nt], a, bf[nt]);
            }
        }
        __syncthreads();
    }

    // --- epilogue: frags -> smem transpose -> coalesced stores ---
    float* s_o = reinterpret_cast<float*>(smem_raw);  // [cout96][px] pitch 130
    #pragma unroll
    for (int h = 0; h < 2; h++)
        #pragma unroll
        for (int nt = 0; nt < 6; nt++) {
            int m = m0 + h*16 + gid;
            int n = n0 + nt*8 + 2*qid;
            s_o[n*130 + m]           = acc[h][nt][0];
            s_o[(n+1)*130 + m]       = acc[h][nt][1];
            s_o[n*130 + m + 8]       = acc[h][nt][2];
            s_o[(n+1)*130 + m + 8]   = acc[h][nt][3];
        }
    __syncthreads();

    // main output (fp32, complex-interleaved layout)
    for (int i = tid; i < FF*STRIP; i += 256) {
        int f  = i >> 7;
        int px = i & (STRIP-1);
        float v0 = s_o[f*130 + px]        + bg[f];
        float v1 = s_o[(f+FF)*130 + px]   + bg[f+FF];
        reinterpret_cast<float2*>(out)[((size_t)(LAYER*BB + b)*FF + f)*HWW + base + px]
            = make_float2(v0, v1);
    }
    // sigma'd half output for next layer
    if (LAYER == 1) {
        for (int i = tid; i < NCH*STRIP; i += 256) {
            int ci = i >> 7;
            int px = i & (STRIP-1);
            uint32_t u[8];
            #pragma unroll
            for (int j2 = 0; j2 < 8; j2++) {
                int c0 = ci*CHUNK + 2*j2;
                float v0 = s_o[c0*130 + px]     + bg[c0];
                float v1 = s_o[(c0+1)*130 + px] + bg[c0+1];
                __half2 hh = __floats2half2_rn(sigma_f(v0), sigma_f(v1));
                u[j2] = *reinterpret_cast<uint32_t*>(&hh);
            }
            uint4* dst = reinterpret_cast<uint4*>(
                g_sig1 + ((size_t)(b*NCH + ci)*HWW + base + px)*CHUNK);
            dst[0] = make_uint4(u[0], u[1], u[2], u[3]);
            dst[1] = make_uint4(u[4], u[5], u[6], u[7]);
        }
    }
}

// ---------------------------------------------------------------------------
// Border fixup: recompute columns x=0 and x=319 for layer L (x-wrap repair).
// ---------------------------------------------------------------------------
template<int LAYER>
__global__ __launch_bounds__(96)
void fixup_kernel(float* __restrict__ out) {
    const __half* __restrict__ sig_in = (LAYER == 1) ? g_sig0 : g_sig1;
    const __half* __restrict__ wg     = (LAYER == 1) ? g_w1 : g_w2;
    const float*  __restrict__ bg     = (LAYER == 1) ? g_b1 : g_b2;

    int blk  = blockIdx.x;
    int side = blk & 1;
    int y    = (blk >> 1) % HH;
    int b    = (blk >> 1) / HH;
    int x    = side ? (WW-1) : 0;
    int xs   = side ? (WW-2) : 0;
    int cout = threadIdx.x;

    __shared__ float s_act[3][2][CC];
    for (int i = cout; i < 3*2*CC; i += 96) {
        int c   = i % CC;
        int dxl = (i / CC) % 2;
        int dy  = i / (2*CC);
        int yy  = y + dy - 1;
        float v = 0.0f;
        if (yy >= 0 && yy < HH)
            v = __half2float(sig_in[((size_t)(b*NCH + c/CHUNK)*HWW
                                     + yy*WW + xs + dxl)*CHUNK + (c % CHUNK)]);
        s_act[dy][dxl][c] = v;
    }
    __syncthreads();

    float acc = bg[cout];
    #pragma unroll
    for (int dy = 0; dy < 3; dy++)
        #pragma unroll
        for (int dx = 0; dx < 3; dx++) {
            int xx = x + dx - 1;
            if (xx < 0 || xx >= WW) continue;
            int dxl = xx - xs;
            for (int c = 0; c < CC; c++) {
                float w = __half2float(
                    wg[(((size_t)(c/CHUNK)*9 + dy*3 + dx)*CC + cout)*BPX + (c % CHUNK)]);
                acc = fmaf(w, s_act[dy][dxl][c], acc);
            }
        }

    int p = y*WW + x;
    if (LAYER == 1)
        g_sig1[((size_t)(b*NCH + cout/CHUNK)*HWW + p)*CHUNK + (cout % CHUNK)]
            = __float2half_rn(sigma_f(acc));
    int f = cout % FF, c2 = cout / FF;
    out[(((size_t)(LAYER*BB + b)*FF + f)*HWW + p)*2 + c2] = acc;
}

extern "C" void kernel_launch(void* const* d_in, const int* in_sizes, int n_in,
                              void* d_out, int out_size) {
    const float* x_real = (const float*)d_in[0];
    const float* x_imag = (const float*)d_in[1];
    const float* w0r = (const float*)d_in[2];
    const float* w0i = (const float*)d_in[3];
    const float* b0r = (const float*)d_in[4];
    const float* b0i = (const float*)d_in[5];
    const float* w1r = (const float*)d_in[6];
    const float* w1i = (const float*)d_in[7];
    const float* b1r = (const float*)d_in[8];
    const float* b1i = (const float*)d_in[9];
    const float* w2r = (const float*)d_in[10];
    const float* w2i = (const float*)d_in[11];
    const float* b2r = (const float*)d_in[12];
    const float* b2i = (const float*)d_in[13];
    float* out = (float*)d_out;

    static bool attr_set = false;
    if (!attr_set) {
        cudaFuncSetAttribute(convT_kernel<1>, cudaFuncAttributeMaxDynamicSharedMemorySize, SMEM_BYTES);
        cudaFuncSetAttribute(convT_kernel<2>, cudaFuncAttributeMaxDynamicSharedMemorySize, SMEM_BYTES);
        attr_set = true;
    }

    repack_small<<<(2*9*CC + 255)/256, 256>>>(w0r, w0i, b0r, b0i);
    repack_big<<<(NCH*9*CC*BPX + 255)/256, 256>>>(w1r, w1i, b1r, b1i, 1);
    repack_big<<<(NCH*9*CC*BPX + 255)/256, 256>>>(w2r, w2i, b2r, b2i, 2);

    conv0_kernel<<<(BB*HWW + 255)/256, 256>>>(x_real, x_imag, out);

    dim3 grid(NSTRIP, BB);
    convT_kernel<1><<<grid, 256, SMEM_BYTES>>>(out);
    fixup_kernel<1><<<BB*HH*2, 96>>>(out);
    convT_kernel<2><<<grid, 256, SMEM_BYTES>>>(out);
    fixup_kernel<2><<<BB*HH*2, 96>>>(out);
}

// round 10
// speedup vs baseline: 5.6589x; 1.1243x over previous
#include <cuda_runtime.h>
#include <cuda_fp16.h>
#include <cstdint>

#define BB 2
#define FF 48
#define CC 96
#define HH 320
#define WW 320
#define HWW (HH*WW)

#define STRIP 128
#define NSTRIP (HWW/STRIP)   // 800
#define NJOBS (NSTRIP*BB)    // 1600
#define CHUNK 16
#define NCH (CC/CHUNK)       // 6

// smem: B (all weights) at 0, then two A buffers; s_sig aliases A buffers.
#define SB_BYTES (NCH*9*CC*32)          // 165888 (rows of 32B, XOR-swizzled)
#define ABUF_BYTES 12800                // 390 rows * 32B = 12480, padded to 256B mult
#define SA_OFF SB_BYTES                 // 165888 (256B aligned)
#define SMEM_BYTES (SB_BYTES + 2*ABUF_BYTES)   // 191488
#define SSIG_OFF SB_BYTES               // 24576B needed <= 25600 available

// sigma'd activations, fp16, pixel-interleaved by 16-ch chunk: [b][ci][pix][k16]
__device__ __align__(16) __half g_sig0[(size_t)BB*NCH*HWW*CHUNK];
__device__ __align__(16) __half g_sig1[(size_t)BB*NCH*HWW*CHUNK];
// weights: fp16, [ci][tap][cout96][k16] with 16B XOR swizzle pre-baked
__device__ float  g_w0[2*9*CC];
__device__ __align__(16) __half g_w1[NCH*9*CC*CHUNK];
__device__ __align__(16) __half g_w2[NCH*9*CC*CHUNK];
__device__ float g_b0[CC];
__device__ float g_b1[CC];
__device__ float g_b2[CC];

__device__ __forceinline__ float sigma_f(float u) {
    float quad = fmaf(u, fmaf(u, 250.0f, 0.5f), 0.00025f);
    return (fabsf(u) > 0.001f) ? fmaxf(u, 0.0f) : quad;
}

// 16B XOR swizzle on byte offsets within a 256B-aligned region:
// rows (32B) with bit2 set swap their two 16B halves -> conflict-free LDS/ldmatrix
__device__ __forceinline__ uint32_t swz(uint32_t off) {
    return off ^ ((off & 128u) >> 3);
}
__device__ __host__ __forceinline__ int swz_half_idx(int h) {   // same transform on half index
    return h ^ ((h >> 3) & 8);
}

__device__ __forceinline__ uint32_t smem_u32(const void* p) {
    return (uint32_t)__cvta_generic_to_shared(p);
}
__device__ __forceinline__ uint32_t lds32(uint32_t addr) {
    uint32_t v; asm volatile("ld.shared.b32 %0, [%1];" : "=r"(v) : "r"(addr)); return v;
}
__device__ __forceinline__ void ldmA(uint32_t* r, uint32_t addr) {
    asm volatile("ldmatrix.sync.aligned.m8n8.x4.shared.b16 {%0,%1,%2,%3}, [%4];"
        : "=r"(r[0]), "=r"(r[1]), "=r"(r[2]), "=r"(r[3]) : "r"(addr));
}
__device__ __forceinline__ void mma_f16(float* d, const uint32_t* a, const uint32_t* b) {
    asm("mma.sync.aligned.m16n8k16.row.col.f32.f16.f16.f32 "
        "{%0,%1,%2,%3}, {%4,%5,%6,%7}, {%8,%9}, {%0,%1,%2,%3};"
        : "+f"(d[0]), "+f"(d[1]), "+f"(d[2]), "+f"(d[3])
        : "r"(a[0]), "r"(a[1]), "r"(a[2]), "r"(a[3]), "r"(b[0]), "r"(b[1]));
}
__device__ __forceinline__ void cp16(uint32_t dst, const void* src, bool valid) {
    int sz = valid ? 16 : 0;
    asm volatile("cp.async.cg.shared.global [%0], [%1], 16, %2;"
                 :: "r"(dst), "l"(src), "r"(sz) : "memory");
}
#define CP_COMMIT() asm volatile("cp.async.commit_group;" ::: "memory")
#define CP_WAIT(n)  asm volatile("cp.async.wait_group %0;" :: "n"(n) : "memory")

// ---------------------------------------------------------------------------
// Weight repack: complex (wr, wi) -> fp16 [ci][tap][cout][k16], swizzle baked
// ---------------------------------------------------------------------------
__global__ void repack_big(const float* __restrict__ wr, const float* __restrict__ wi,
                           const float* __restrict__ br, const float* __restrict__ bi,
                           int which) {
    __half* dw = (which == 1) ? g_w1 : g_w2;
    float*  db = (which == 1) ? g_b1 : g_b2;
    int idx = blockIdx.x * blockDim.x + threadIdx.x;
    if (idx < CC) db[idx] = (idx < FF) ? br[idx] : bi[idx - FF];
    if (idx >= NCH*9*CC*CHUNK) return;
    int k    = idx % CHUNK;
    int cout = (idx / CHUNK) % CC;
    int t    = (idx / (CHUNK*CC)) % 9;
    int ci   = idx / (CHUNK*CC*9);
    int cin = ci*CHUNK + k;
    int fo = cout % FF, fi = cin % FF;
    const float* src = ((cout < FF) == (cin < FF)) ? wr : wi;
    float v = src[(fo*FF + fi)*9 + t];
    if (cout < FF && cin >= FF) v = -v;
    dw[swz_half_idx(idx)] = __float2half_rn(v);
}

__global__ void repack_small(const float* __restrict__ wr, const float* __restrict__ wi,
                             const float* __restrict__ br, const float* __restrict__ bi) {
    int idx = blockIdx.x * blockDim.x + threadIdx.x;
    if (idx < CC) g_b0[idx] = (idx < FF) ? br[idx] : bi[idx - FF];
    if (idx >= 2*9*CC) return;
    int cout = idx % CC;
    int t    = (idx / CC) % 9;
    int cin  = idx / (9*CC);
    int fo = cout % FF;
    const float* src = ((cout < FF) == (cin == 0)) ? wr : wi;
    float v = src[fo*9 + t];
    if (cout < FF && cin == 1) v = -v;
    g_w0[idx] = v;
}

// ---------------------------------------------------------------------------
// Layer 0: conv 2 -> 96, exact fp32; writes out + g_sig0 (half, interleaved)
// ---------------------------------------------------------------------------
__global__ __launch_bounds__(256)
void conv0_kernel(const float* __restrict__ xr, const float* __restrict__ xi,
                  float* __restrict__ out) {
    __shared__ float sw[2*9*CC];
    __shared__ float sb[CC];
    for (int i = threadIdx.x; i < 2*9*CC; i += 256) sw[i] = g_w0[i];
    if (threadIdx.x < CC) sb[threadIdx.x] = g_b0[threadIdx.x];
    __syncthreads();

    int pix = blockIdx.x * 256 + threadIdx.x;
    if (pix >= BB*HWW) return;
    int b = pix / HWW;
    int p = pix - b*HWW;
    int y = p / WW, x = p - y*WW;

    const float* x0 = xr + b*HWW;
    const float* x1 = xi + b*HWW;
    float in[18];
    #pragma unroll
    for (int dy = 0; dy < 3; dy++) {
        #pragma unroll
        for (int dx = 0; dx < 3; dx++) {
            int yy = y + dy - 1, xx = x + dx - 1;
            bool ok = (yy >= 0) && (yy < HH) && (xx >= 0) && (xx < WW);
            in[dy*3 + dx]     = ok ? x0[yy*WW + xx] : 0.0f;
            in[9 + dy*3 + dx] = ok ? x1[yy*WW + xx] : 0.0f;
        }
    }

    for (int ci = 0; ci < NCH; ci++) {
        uint32_t u[8];
        #pragma unroll
        for (int j2 = 0; j2 < 8; j2++) {
            float a2[2];
            #pragma unroll
            for (int s = 0; s < 2; s++) {
                int cout = ci*CHUNK + 2*j2 + s;
                float acc = sb[cout];
                #pragma unroll
                for (int t = 0; t < 18; t++)
                    acc = fmaf(in[t], sw[t*CC + cout], acc);
                int f = cout % FF, c2 = cout / FF;
                out[((b*FF + f)*HWW + p)*2 + c2] = acc;
                a2[s] = sigma_f(acc);
            }
            __half2 hh = __floats2half2_rn(a2[0], a2[1]);
            u[j2] = *reinterpret_cast<uint32_t*>(&hh);
        }
        uint4* dst = reinterpret_cast<uint4*>(
            g_sig0 + ((size_t)(b*NCH + ci)*HWW + p)*CHUNK);
        dst[0] = make_uint4(u[0], u[1], u[2], u[3]);
        dst[1] = make_uint4(u[4], u[5], u[6], u[7]);
    }
}

// ---------------------------------------------------------------------------
// Layers 1,2: persistent-weight fp16 m16n8k16 implicit GEMM.
// Grid = 148 CTAs x 256 thr (8 warps), 1 CTA/SM; each CTA loops strips.
// Weights (166KB, swizzled) staged ONCE; A double-buffered via cp.async.
// Warp tile: m=32 px, n = {n0..n0+23} U {n0+48..n0+71} (real/imag pairs)
// -> epilogue writes float2 straight from fragments.
// Row-wrap at x=0/319 wrong by construction -> fixup repairs.
// ---------------------------------------------------------------------------
template<int LAYER>
__global__ __launch_bounds__(256, 1)
void convT_kernel(float* __restrict__ out) {
    extern __shared__ __align__(256) char smem_raw[];
    uint32_t sb_base = smem_u32(smem_raw);
    uint32_t sa_base[2] = { sb_base + SA_OFF, sb_base + SA_OFF + ABUF_BYTES };
    __half* s_sig = reinterpret_cast<__half*>(smem_raw + SSIG_OFF);

    const __half* __restrict__ sig_in = (LAYER == 1) ? g_sig0 : g_sig1;
    const __half* __restrict__ wg     = (LAYER == 1) ? g_w1 : g_w2;
    const float*  __restrict__ bg     = (LAYER == 1) ? g_b1 : g_b2;

    int tid  = threadIdx.x;
    int warp = tid >> 5, lane = tid & 31;
    int m0 = (warp >> 1) * 32;
    int n0 = (warp & 1) * 24;
    int gid = lane >> 2, qid = lane & 3;
    int arow = lane & 15;
    uint32_t akoff = (uint32_t)(lane >> 4) * 16;

    // stage ALL weights once (swizzle pre-baked -> flat memcpy)
    {
        const uint4* srcw = reinterpret_cast<const uint4*>(wg);
        uint4* dstw = reinterpret_cast<uint4*>(smem_raw);
        for (int i = tid; i < SB_BYTES/16; i += 256) dstw[i] = srcw[i];
    }
    __syncthreads();

    for (int job = blockIdx.x; job < NJOBS; job += gridDim.x) {
        int b     = job / NSTRIP;
        int strip = job - b*NSTRIP;
        int base  = strip * STRIP;
        const __half* plane0 = sig_in + (size_t)b*NCH*HWW*CHUNK;

        float acc[2][6][4];
        #pragma unroll
        for (int h = 0; h < 2; h++)
            #pragma unroll
            for (int nt = 0; nt < 6; nt++)
                #pragma unroll
                for (int r = 0; r < 4; r++) acc[h][nt][r] = 0.0f;

        // prefetch chunk 0
        {
            const __half* pc = plane0;
            for (int i = tid; i < 2*390; i += 256) {
                int blk = i >> 1, hi = i & 1;
                int dyr = blk / 130, px = blk - dyr*130;
                int fl  = base + (dyr - 1)*WW + px - 1;
                bool ok = (fl >= 0) && (fl < HWW);
                cp16(sa_base[0] + swz((uint32_t)(blk*32 + hi*16)),
                     pc + ((size_t)(ok ? fl : 0))*CHUNK + hi*8, ok);
            }
        }
        CP_COMMIT();

        for (int ci = 0; ci < NCH; ci++) {
            if (ci + 1 < NCH) {
                const __half* pc = plane0 + (size_t)(ci+1)*HWW*CHUNK;
                uint32_t ab = sa_base[(ci+1) & 1];
                for (int i = tid; i < 2*390; i += 256) {
                    int blk = i >> 1, hi = i & 1;
                    int dyr = blk / 130, px = blk - dyr*130;
                    int fl  = base + (dyr - 1)*WW + px - 1;
                    bool ok = (fl >= 0) && (fl < HWW);
                    cp16(ab + swz((uint32_t)(blk*32 + hi*16)),
                         pc + ((size_t)(ok ? fl : 0))*CHUNK + hi*8, ok);
                }
                CP_COMMIT();
                CP_WAIT(1);
            } else {
                CP_WAIT(0);
            }
            __syncthreads();

            uint32_t sa = sa_base[ci & 1];
            uint32_t cioff = (uint32_t)ci * (9*CC*32);
            #pragma unroll
            for (int tap = 0; tap < 9; tap++) {
                int dy = tap / 3, dx = tap - dy*3;
                uint32_t boff = cioff + (uint32_t)tap * (CC*32);
                uint32_t bf[6][2];
                #pragma unroll
                for (int nt = 0; nt < 6; nt++) {
                    int nrow = ((nt < 3) ? (n0 + nt*8) : (48 + n0 + (nt-3)*8)) + gid;
                    uint32_t o = boff + (uint32_t)nrow*32 + (uint32_t)qid*4;
                    bf[nt][0] = lds32(sb_base + swz(o));
                    bf[nt][1] = lds32(sb_base + swz(o + 16));
                }
                #pragma unroll
                for (int h = 0; h < 2; h++) {
                    int p = dy*130 + dx + m0 + h*16 + arow;
                    uint32_t a[4];
                    ldmA(a, sa + swz((uint32_t)p*32 + akoff));
                    #pragma unroll
                    for (int nt = 0; nt < 6; nt++)
                        mma_f16(acc[h][nt], a, bf[nt]);
                }
            }
            __syncthreads();
        }

        // --- epilogue: direct float2 stores from fragments ---
        float2* ob = reinterpret_cast<float2*>(out)
                   + (size_t)(LAYER*BB + b)*FF*HWW + base;
        #pragma unroll
        for (int h = 0; h < 2; h++) {
            int m = m0 + h*16 + gid;
            #pragma unroll
            for (int nt = 0; nt < 3; nt++) {
                int n = n0 + nt*8 + 2*qid;
                float br0 = __ldg(bg + n),      br1 = __ldg(bg + n + 1);
                float bi0 = __ldg(bg + n + 48), bi1 = __ldg(bg + n + 49);
                float re0 = acc[h][nt][0] + br0, re1 = acc[h][nt][1] + br1;
                float re2 = acc[h][nt][2] + br0, re3 = acc[h][nt][3] + br1;
                float im0 = acc[h][nt+3][0] + bi0, im1 = acc[h][nt+3][1] + bi1;
                float im2 = acc[h][nt+3][2] + bi0, im3 = acc[h][nt+3][3] + bi1;
                ob[(size_t)n*HWW + m]         = make_float2(re0, im0);
                ob[(size_t)(n+1)*HWW + m]     = make_float2(re1, im1);
                ob[(size_t)n*HWW + m + 8]     = make_float2(re2, im2);
                ob[(size_t)(n+1)*HWW + m + 8] = make_float2(re3, im3);
                if (LAYER == 1) {
                    __half2* sg;
                    sg = reinterpret_cast<__half2*>(s_sig + m*CC + n);
                    *sg = __floats2half2_rn(sigma_f(re0), sigma_f(re1));
                    sg = reinterpret_cast<__half2*>(s_sig + m*CC + n + 48);
                    *sg = __floats2half2_rn(sigma_f(im0), sigma_f(im1));
                    sg = reinterpret_cast<__half2*>(s_sig + (m+8)*CC + n);
                    *sg = __floats2half2_rn(sigma_f(re2), sigma_f(re3));
                    sg = reinterpret_cast<__half2*>(s_sig + (m+8)*CC + n + 48);
                    *sg = __floats2half2_rn(sigma_f(im2), sigma_f(im3));
                }
            }
        }
        if (LAYER == 1) {
            __syncthreads();
            for (int i = tid; i < NCH*STRIP; i += 256) {
                int ci = i >> 7;
                int px = i & (STRIP-1);
                const uint4* srcv = reinterpret_cast<const uint4*>(
                    s_sig + px*CC + ci*CHUNK);
                uint4* dst = reinterpret_cast<uint4*>(
                    g_sig1 + ((size_t)(b*NCH + ci)*HWW + base + px)*CHUNK);
                dst[0] = srcv[0];
                dst[1] = srcv[1];
            }
            __syncthreads();   // s_sig aliases A buffers: done before next prefetch
        }
    }
}

// ---------------------------------------------------------------------------
// Border fixup: recompute columns x=0 and x=319 for layer L (x-wrap repair).
// ---------------------------------------------------------------------------
template<int LAYER>
__global__ __launch_bounds__(96)
void fixup_kernel(float* __restrict__ out) {
    const __half* __restrict__ sig_in = (LAYER == 1) ? g_sig0 : g_sig1;
    const __half* __restrict__ wg     = (LAYER == 1) ? g_w1 : g_w2;
    const float*  __restrict__ bg     = (LAYER == 1) ? g_b1 : g_b2;

    int blk  = blockIdx.x;
    int side = blk & 1;
    int y    = (blk >> 1) % HH;
    int b    = (blk >> 1) / HH;
    int x    = side ? (WW-1) : 0;
    int xs   = side ? (WW-2) : 0;
    int cout = threadIdx.x;

    __shared__ float s_act[3][2][CC];
    for (int i = cout; i < 3*2*CC; i += 96) {
        int c   = i % CC;
        int dxl = (i / CC) % 2;
        int dy  = i / (2*CC);
        int yy  = y + dy - 1;
        float v = 0.0f;
        if (yy >= 0 && yy < HH)
            v = __half2float(sig_in[((size_t)(b*NCH + c/CHUNK)*HWW
                                     + yy*WW + xs + dxl)*CHUNK + (c % CHUNK)]);
        s_act[dy][dxl][c] = v;
    }
    __syncthreads();

    float acc = bg[cout];
    #pragma unroll
    for (int dy = 0; dy < 3; dy++)
        #pragma unroll
        for (int dx = 0; dx < 3; dx++) {
            int xx = x + dx - 1;
            if (xx < 0 || xx >= WW) continue;
            int dxl = xx - xs;
            for (int c = 0; c < CC; c++) {
                int hidx = (((c/CHUNK)*9 + dy*3 + dx)*CC + cout)*CHUNK + (c % CHUNK);
                float w = __half2float(wg[swz_half_idx(hidx)]);
                acc = fmaf(w, s_act[dy][dxl][c], acc);
            }
        }

    int p = y*WW + x;
    if (LAYER == 1)
        g_sig1[((size_t)(b*NCH + cout/CHUNK)*HWW + p)*CHUNK + (cout % CHUNK)]
            = __float2half_rn(sigma_f(acc));
    int f = cout % FF, c2 = cout / FF;
    out[(((size_t)(LAYER*BB + b)*FF + f)*HWW + p)*2 + c2] = acc;
}

extern "C" void kernel_launch(void* const* d_in, const int* in_sizes, int n_in,
                              void* d_out, int out_size) {
    const float* x_real = (const float*)d_in[0];
    const float* x_imag = (const float*)d_in[1];
    const float* w0r = (const float*)d_in[2];
    const float* w0i = (const float*)d_in[3];
    const float* b0r = (const float*)d_in[4];
    const float* b0i = (const float*)d_in[5];
    const float* w1r = (const float*)d_in[6];
    const float* w1i = (const float*)d_in[7];
    const float* b1r = (const float*)d_in[8];
    const float* b1i = (const float*)d_in[9];
    const float* w2r = (const float*)d_in[10];
    const float* w2i = (const float*)d_in[11];
    const float* b2r = (const float*)d_in[12];
    const float* b2i = (const float*)d_in[13];
    float* out = (float*)d_out;

    static bool attr_set = false;
    if (!attr_set) {
        cudaFuncSetAttribute(convT_kernel<1>, cudaFuncAttributeMaxDynamicSharedMemorySize, SMEM_BYTES);
        cudaFuncSetAttribute(convT_kernel<2>, cudaFuncAttributeMaxDynamicSharedMemorySize, SMEM_BYTES);
        attr_set = true;
    }

    repack_small<<<(2*9*CC + 255)/256, 256>>>(w0r, w0i, b0r, b0i);
    repack_big<<<(NCH*9*CC*CHUNK + 255)/256, 256>>>(w1r, w1i, b1r, b1i, 1);
    repack_big<<<(NCH*9*CC*CHUNK + 255)/256, 256>>>(w2r, w2i, b2r, b2i, 2);

    conv0_kernel<<<(BB*HWW + 255)/256, 256>>>(x_real, x_imag, out);

    convT_kernel<1><<<148, 256, SMEM_BYTES>>>(out);
    fixup_kernel<1><<<BB*HH*2, 96>>>(out);
    convT_kernel<2><<<148, 256, SMEM_BYTES>>>(out);
    fixup_kernel<2><<<BB*HH*2, 96>>>(out);
}